// round 6
// baseline (speedup 1.0000x reference)
#include <cuda_runtime.h>
#include <math.h>

#define D_MODEL 1024
#define N_HEAD  16
#define D_HEAD  64
#define B_      2
#define T_      2048
#define M_TOK   (B_ * T_)              // 4096
#define N_QKV   (3 * N_HEAD * D_HEAD)  // 3072

// ---------------- scratch (device globals; no allocation allowed) ------------
__device__ float g_q[B_ * N_HEAD * T_ * D_HEAD];   // (B,H,T,dh)
__device__ float g_k[B_ * N_HEAD * T_ * D_HEAD];
__device__ float g_v[B_ * N_HEAD * T_ * D_HEAD];
__device__ float g_ov[M_TOK * D_MODEL];            // attn_vec in (B,T,H*dh)
__device__ float g_y[M_TOK * D_MODEL];             // inp + attn_out

// ---------------- helpers ----------------------------------------------------
__device__ __forceinline__ unsigned f2t(float x) {
    unsigned u;
    asm("cvt.rna.tf32.f32 %0, %1;" : "=r"(u) : "f"(x));
    return u;
}

__device__ __forceinline__ void mma8(float* c,
                                     unsigned a0, unsigned a1, unsigned a2, unsigned a3,
                                     unsigned b0, unsigned b1) {
    asm volatile(
        "mma.sync.aligned.m16n8k8.row.col.f32.tf32.tf32.f32 "
        "{%0,%1,%2,%3}, {%4,%5,%6,%7}, {%8,%9}, {%0,%1,%2,%3};\n"
        : "+f"(c[0]), "+f"(c[1]), "+f"(c[2]), "+f"(c[3])
        : "r"(a0), "r"(a1), "r"(a2), "r"(a3), "r"(b0), "r"(b1));
}

__device__ __forceinline__ void cp16(float* dst_smem, const float* src) {
    unsigned d = (unsigned)__cvta_generic_to_shared(dst_smem);
    asm volatile(
        "{ .reg .u64 gp; cvta.to.global.u64 gp, %1;"
        "  cp.async.cg.shared.global [%0], [gp], 16; }\n"
        :: "r"(d), "l"(src) : "memory");
}
#define CP_COMMIT asm volatile("cp.async.commit_group;\n" ::: "memory")
#define CP_WAIT0  asm volatile("cp.async.wait_group 0;\n" ::: "memory")

// =============================================================================
// GEMMs: block 128x128, 8 warps (2m x 4n), warp 64x32 (4x4 atoms), k-step 32,
// cp.async double-buffered, raw fp32 in smem, tf32 cvt at fragment load.
// =============================================================================
#define GP 36
#define GEMM_SMEM (2 * 2 * 128 * GP * 4)   // 73728 B

__global__ __launch_bounds__(256) void qkv_gemm(const float* __restrict__ A,
                                                const float* __restrict__ W,
                                                const float* __restrict__ bias) {
    extern __shared__ float gsm[];
    float* Asb = gsm;                    // [2][128][GP]
    float* Bsb = gsm + 2 * 128 * GP;
    const int tid = threadIdx.x;
    const int m0 = blockIdx.y * 128, n0 = blockIdx.x * 128;
    const int w = tid >> 5, lane = tid & 31;
    const int g = lane >> 2, l = lane & 3;
    const int wm = (w >> 2) * 64, wn = (w & 3) * 32;

    float acc[4][4][4];
#pragma unroll
    for (int mi = 0; mi < 4; mi++)
#pragma unroll
        for (int ni = 0; ni < 4; ni++)
#pragma unroll
            for (int c = 0; c < 4; c++) acc[mi][ni][c] = 0.f;

    // prologue load
    {
        float* Ad = Asb; float* Bd = Bsb;
#pragma unroll
        for (int s4 = 0; s4 < 4; s4++) {
            const int idx = tid + s4 * 256;
            const int r = idx >> 3, c = (idx & 7) * 4;
            cp16(Ad + r * GP + c, A + (size_t)(m0 + r) * D_MODEL + c);
            cp16(Bd + r * GP + c, W + (size_t)(n0 + r) * D_MODEL + c);
        }
        CP_COMMIT;
    }

    for (int kt = 0; kt < 32; kt++) {
        CP_WAIT0;
        __syncthreads();
        if (kt < 31) {
            const int ko = (kt + 1) * 32;
            float* Ad = Asb + ((kt + 1) & 1) * 128 * GP;
            float* Bd = Bsb + ((kt + 1) & 1) * 128 * GP;
#pragma unroll
            for (int s4 = 0; s4 < 4; s4++) {
                const int idx = tid + s4 * 256;
                const int r = idx >> 3, c = (idx & 7) * 4;
                cp16(Ad + r * GP + c, A + (size_t)(m0 + r) * D_MODEL + ko + c);
                cp16(Bd + r * GP + c, W + (size_t)(n0 + r) * D_MODEL + ko + c);
            }
            CP_COMMIT;
        }
        const float* As = Asb + (kt & 1) * 128 * GP;
        const float* Bs = Bsb + (kt & 1) * 128 * GP;
#pragma unroll
        for (int ka = 0; ka < 4; ka++) {
            const int kk = ka * 8;
            unsigned af[4][4], bf[4][2];
#pragma unroll
            for (int mi = 0; mi < 4; mi++) {
                const int r = wm + mi * 16 + g;
                af[mi][0] = f2t(As[r * GP + kk + l]);
                af[mi][1] = f2t(As[(r + 8) * GP + kk + l]);
                af[mi][2] = f2t(As[r * GP + kk + l + 4]);
                af[mi][3] = f2t(As[(r + 8) * GP + kk + l + 4]);
            }
#pragma unroll
            for (int ni = 0; ni < 4; ni++) {
                const int c = wn + ni * 8 + g;
                bf[ni][0] = f2t(Bs[c * GP + kk + l]);
                bf[ni][1] = f2t(Bs[c * GP + kk + l + 4]);
            }
#pragma unroll
            for (int mi = 0; mi < 4; mi++)
#pragma unroll
                for (int ni = 0; ni < 4; ni++)
                    mma8(acc[mi][ni], af[mi][0], af[mi][1], af[mi][2], af[mi][3],
                         bf[ni][0], bf[ni][1]);
        }
    }

    // epilogue: +bias, scatter into (B,H,T,dh) q/k/v
#pragma unroll
    for (int mi = 0; mi < 4; mi++) {
#pragma unroll
        for (int rs_ = 0; rs_ < 2; rs_++) {
            const int mm = m0 + wm + mi * 16 + g + rs_ * 8;
            const int b = mm >> 11, t = mm & (T_ - 1);
#pragma unroll
            for (int ni = 0; ni < 4; ni++) {
                const int o = n0 + wn + ni * 8 + 2 * l;
                float2 bb = *(const float2*)(bias + o);
                float2 v;
                v.x = acc[mi][ni][rs_ * 2]     + bb.x;
                v.y = acc[mi][ni][rs_ * 2 + 1] + bb.y;
                const int part = o >> 10, rem = o & 1023;
                const int h = rem >> 6, d = rem & 63;
                const size_t idx = ((size_t)(b * N_HEAD + h) * T_ + t) * D_HEAD + d;
                if (part == 0)      *(float2*)&g_q[idx] = v;
                else if (part == 1) *(float2*)&g_k[idx] = v;
                else                *(float2*)&g_v[idx] = v;
            }
        }
    }
}

__global__ __launch_bounds__(256) void o_gemm(const float* __restrict__ Wo,
                                              const float* __restrict__ inp) {
    extern __shared__ float gsm[];
    float* Asb = gsm;
    float* Bsb = gsm + 2 * 128 * GP;
    const int tid = threadIdx.x;
    const int m0 = blockIdx.y * 128, n0 = blockIdx.x * 128;
    const int w = tid >> 5, lane = tid & 31;
    const int g = lane >> 2, l = lane & 3;
    const int wm = (w >> 2) * 64, wn = (w & 3) * 32;

    float acc[4][4][4];
#pragma unroll
    for (int mi = 0; mi < 4; mi++)
#pragma unroll
        for (int ni = 0; ni < 4; ni++)
#pragma unroll
            for (int c = 0; c < 4; c++) acc[mi][ni][c] = 0.f;

    {
        float* Ad = Asb; float* Bd = Bsb;
#pragma unroll
        for (int s4 = 0; s4 < 4; s4++) {
            const int idx = tid + s4 * 256;
            const int r = idx >> 3, c = (idx & 7) * 4;
            cp16(Ad + r * GP + c, g_ov + (size_t)(m0 + r) * D_MODEL + c);
            cp16(Bd + r * GP + c, Wo + (size_t)(n0 + r) * D_MODEL + c);
        }
        CP_COMMIT;
    }

    for (int kt = 0; kt < 32; kt++) {
        CP_WAIT0;
        __syncthreads();
        if (kt < 31) {
            const int ko = (kt + 1) * 32;
            float* Ad = Asb + ((kt + 1) & 1) * 128 * GP;
            float* Bd = Bsb + ((kt + 1) & 1) * 128 * GP;
#pragma unroll
            for (int s4 = 0; s4 < 4; s4++) {
                const int idx = tid + s4 * 256;
                const int r = idx >> 3, c = (idx & 7) * 4;
                cp16(Ad + r * GP + c, g_ov + (size_t)(m0 + r) * D_MODEL + ko + c);
                cp16(Bd + r * GP + c, Wo + (size_t)(n0 + r) * D_MODEL + ko + c);
            }
            CP_COMMIT;
        }
        const float* As = Asb + (kt & 1) * 128 * GP;
        const float* Bs = Bsb + (kt & 1) * 128 * GP;
#pragma unroll
        for (int ka = 0; ka < 4; ka++) {
            const int kk = ka * 8;
            unsigned af[4][4], bf[4][2];
#pragma unroll
            for (int mi = 0; mi < 4; mi++) {
                const int r = wm + mi * 16 + g;
                af[mi][0] = f2t(As[r * GP + kk + l]);
                af[mi][1] = f2t(As[(r + 8) * GP + kk + l]);
                af[mi][2] = f2t(As[r * GP + kk + l + 4]);
                af[mi][3] = f2t(As[(r + 8) * GP + kk + l + 4]);
            }
#pragma unroll
            for (int ni = 0; ni < 4; ni++) {
                const int c = wn + ni * 8 + g;
                bf[ni][0] = f2t(Bs[c * GP + kk + l]);
                bf[ni][1] = f2t(Bs[c * GP + kk + l + 4]);
            }
#pragma unroll
            for (int mi = 0; mi < 4; mi++)
#pragma unroll
                for (int ni = 0; ni < 4; ni++)
                    mma8(acc[mi][ni], af[mi][0], af[mi][1], af[mi][2], af[mi][3],
                         bf[ni][0], bf[ni][1]);
        }
    }

#pragma unroll
    for (int mi = 0; mi < 4; mi++) {
#pragma unroll
        for (int rs_ = 0; rs_ < 2; rs_++) {
            const int mm = m0 + wm + mi * 16 + g + rs_ * 8;
#pragma unroll
            for (int ni = 0; ni < 4; ni++) {
                const int o = n0 + wn + ni * 8 + 2 * l;
                const size_t idx = (size_t)mm * D_MODEL + o;
                float2 r2 = *(const float2*)(inp + idx);
                float2 v;
                v.x = acc[mi][ni][rs_ * 2]     + r2.x;
                v.y = acc[mi][ni][rs_ * 2 + 1] + r2.y;
                *(float2*)&g_y[idx] = v;
            }
        }
    }
}

// =============================================================================
// Flash attention: 8 warps, each owns 16 full query rows (QB=128, KB=64).
// Q fragments persistent in registers; softmax fully in registers;
// P C-frag -> A-frag via shuffles; K cp.async double-buffered; V pipelined
// through registers into transposed smem. One __syncthreads per k-iter.
// =============================================================================
#define AP 68
#define ATT_SMEM ((2 * 64 * AP + 2 * 64 * AP) * 4)   // 69632 B

__global__ __launch_bounds__(256) void attn_kernel() {
    extern __shared__ float asm_[];
    float* Ksm = asm_;                  // [2][64][AP]  K tiles (also Q staging)
    float* Vsm = asm_ + 2 * 64 * AP;    // [2][64][AP]  V transposed [d][key]

    const int bh = blockIdx.y;
    const int qb = blockIdx.x * 128;
    const float* Qg = g_q + (size_t)bh * T_ * D_HEAD;
    const float* Kg = g_k + (size_t)bh * T_ * D_HEAD;
    const float* Vg = g_v + (size_t)bh * T_ * D_HEAD;

    const int tid = threadIdx.x;
    const int w = tid >> 5, lane = tid & 31;
    const int g = lane >> 2, l = lane & 3;
    const int qr = w * 16;

    // ---- stage Q through smem, load fragments to registers (scaled) ----
#pragma unroll
    for (int s4 = 0; s4 < 8; s4++) {
        const int idx = tid + s4 * 256;          // 128 rows x 16 float4
        const int r = idx >> 4, c = (idx & 15) * 4;
        cp16(Ksm + r * AP + c, Qg + (size_t)(qb + r) * D_HEAD + c);
    }
    CP_COMMIT; CP_WAIT0;
    __syncthreads();

    unsigned qa[8][4];
#pragma unroll
    for (int ka = 0; ka < 8; ka++) {
        const int kk = ka * 8;
        qa[ka][0] = f2t(Ksm[(qr + g) * AP + kk + l] * 0.125f);
        qa[ka][1] = f2t(Ksm[(qr + 8 + g) * AP + kk + l] * 0.125f);
        qa[ka][2] = f2t(Ksm[(qr + g) * AP + kk + l + 4] * 0.125f);
        qa[ka][3] = f2t(Ksm[(qr + 8 + g) * AP + kk + l + 4] * 0.125f);
    }
    __syncthreads();   // all warps done reading Q staging before K overwrites

    // ---- preload iter 0 ----
    const int vr = tid & 63, vcq = tid >> 6;     // V loader mapping
    float4 vcur[4], vnxt[4];
    {
#pragma unroll
        for (int s4 = 0; s4 < 4; s4++) {
            const int idx = tid + s4 * 256;      // 64 rows x 16 float4
            const int r = idx >> 4, c = (idx & 15) * 4;
            cp16(Ksm + r * AP + c, Kg + (size_t)r * D_HEAD + c);
        }
        CP_COMMIT;
#pragma unroll
        for (int j = 0; j < 4; j++)
            vcur[j] = *(const float4*)(Vg + (size_t)vr * D_HEAD + vcq * 16 + j * 4);
    }

    float oa[8][4];
#pragma unroll
    for (int ni = 0; ni < 8; ni++)
#pragma unroll
        for (int c = 0; c < 4; c++) oa[ni][c] = 0.f;
    float m0r = -1e30f, m1r = -1e30f, l0r = 0.f, l1r = 0.f;

    const int src0 = (lane & 28) | (l >> 1);
    const int src1 = src0 + 2;
    const bool odd = (l & 1);

    for (int it = 0; it < 32; it++) {
        CP_WAIT0;
        // store V (transposed) for this iter
        {
            float* Vb = Vsm + (it & 1) * 64 * AP;
#pragma unroll
            for (int j = 0; j < 4; j++) {
                const int d = vcq * 16 + j * 4;
                Vb[(d + 0) * AP + vr] = vcur[j].x;
                Vb[(d + 1) * AP + vr] = vcur[j].y;
                Vb[(d + 2) * AP + vr] = vcur[j].z;
                Vb[(d + 3) * AP + vr] = vcur[j].w;
            }
        }
        __syncthreads();
        if (it < 31) {
            const int kb2 = (it + 1) * 64;
            float* Kd = Ksm + ((it + 1) & 1) * 64 * AP;
#pragma unroll
            for (int s4 = 0; s4 < 4; s4++) {
                const int idx = tid + s4 * 256;
                const int r = idx >> 4, c = (idx & 15) * 4;
                cp16(Kd + r * AP + c, Kg + (size_t)(kb2 + r) * D_HEAD + c);
            }
            CP_COMMIT;
#pragma unroll
            for (int j = 0; j < 4; j++)
                vnxt[j] = *(const float4*)(Vg + (size_t)(kb2 + vr) * D_HEAD + vcq * 16 + j * 4);
        }

        const float* Kb = Ksm + (it & 1) * 64 * AP;
        const float* Vb = Vsm + (it & 1) * 64 * AP;

        // ---- S = Q @ K^T ----
        float s[8][4];
#pragma unroll
        for (int ni = 0; ni < 8; ni++)
#pragma unroll
            for (int c = 0; c < 4; c++) s[ni][c] = 0.f;
#pragma unroll
        for (int ka = 0; ka < 8; ka++) {
            const int kk = ka * 8;
            unsigned kf0[8], kf1[8];
#pragma unroll
            for (int ni = 0; ni < 8; ni++) {
                const int c = ni * 8 + g;
                kf0[ni] = f2t(Kb[c * AP + kk + l]);
                kf1[ni] = f2t(Kb[c * AP + kk + l + 4]);
            }
#pragma unroll
            for (int ni = 0; ni < 8; ni++)
                mma8(s[ni], qa[ka][0], qa[ka][1], qa[ka][2], qa[ka][3],
                     kf0[ni], kf1[ni]);
        }

        // ---- register softmax (rows g and g+8, full 64 keys per warp) ----
        float mx0 = -1e30f, mx1 = -1e30f;
#pragma unroll
        for (int ni = 0; ni < 8; ni++) {
            mx0 = fmaxf(mx0, fmaxf(s[ni][0], s[ni][1]));
            mx1 = fmaxf(mx1, fmaxf(s[ni][2], s[ni][3]));
        }
        mx0 = fmaxf(mx0, __shfl_xor_sync(0xffffffffu, mx0, 1, 4));
        mx0 = fmaxf(mx0, __shfl_xor_sync(0xffffffffu, mx0, 2, 4));
        mx1 = fmaxf(mx1, __shfl_xor_sync(0xffffffffu, mx1, 1, 4));
        mx1 = fmaxf(mx1, __shfl_xor_sync(0xffffffffu, mx1, 2, 4));
        const float mn0 = fmaxf(m0r, mx0), mn1 = fmaxf(m1r, mx1);
        const float al0 = __expf(m0r - mn0), al1 = __expf(m1r - mn1);
        m0r = mn0; m1r = mn1;
        float rs0 = 0.f, rs1 = 0.f;
#pragma unroll
        for (int ni = 0; ni < 8; ni++) {
            s[ni][0] = __expf(s[ni][0] - mn0);
            s[ni][1] = __expf(s[ni][1] - mn0);
            s[ni][2] = __expf(s[ni][2] - mn1);
            s[ni][3] = __expf(s[ni][3] - mn1);
            rs0 += s[ni][0] + s[ni][1];
            rs1 += s[ni][2] + s[ni][3];
        }
        rs0 += __shfl_xor_sync(0xffffffffu, rs0, 1, 4);
        rs0 += __shfl_xor_sync(0xffffffffu, rs0, 2, 4);
        rs1 += __shfl_xor_sync(0xffffffffu, rs1, 1, 4);
        rs1 += __shfl_xor_sync(0xffffffffu, rs1, 2, 4);
        l0r = l0r * al0 + rs0;
        l1r = l1r * al1 + rs1;
#pragma unroll
        for (int ni = 0; ni < 8; ni++) {
            oa[ni][0] *= al0; oa[ni][1] *= al0;
            oa[ni][2] *= al1; oa[ni][3] *= al1;
        }

        // cvt P to tf32 in place
#pragma unroll
        for (int ni = 0; ni < 8; ni++)
#pragma unroll
            for (int c = 0; c < 4; c++)
                s[ni][c] = __uint_as_float(f2t(s[ni][c]));

        // ---- O += P @ V : shuffle C-frag -> A-frag per key-block ----
#pragma unroll
        for (int ka = 0; ka < 8; ka++) {
            const float t00 = __shfl_sync(0xffffffffu, s[ka][0], src0);
            const float t01 = __shfl_sync(0xffffffffu, s[ka][1], src0);
            const float t20 = __shfl_sync(0xffffffffu, s[ka][2], src0);
            const float t21 = __shfl_sync(0xffffffffu, s[ka][3], src0);
            const float u00 = __shfl_sync(0xffffffffu, s[ka][0], src1);
            const float u01 = __shfl_sync(0xffffffffu, s[ka][1], src1);
            const float u20 = __shfl_sync(0xffffffffu, s[ka][2], src1);
            const float u21 = __shfl_sync(0xffffffffu, s[ka][3], src1);
            const unsigned pa0 = __float_as_uint(odd ? t01 : t00);
            const unsigned pa1 = __float_as_uint(odd ? t21 : t20);
            const unsigned pa2 = __float_as_uint(odd ? u01 : u00);
            const unsigned pa3 = __float_as_uint(odd ? u21 : u20);
            const int kk = ka * 8;
            unsigned vf0[8], vf1[8];
#pragma unroll
            for (int ni = 0; ni < 8; ni++) {
                const int d = ni * 8 + g;
                vf0[ni] = f2t(Vb[d * AP + kk + l]);
                vf1[ni] = f2t(Vb[d * AP + kk + l + 4]);
            }
#pragma unroll
            for (int ni = 0; ni < 8; ni++)
                mma8(oa[ni], pa0, pa1, pa2, pa3, vf0[ni], vf1[ni]);
        }

#pragma unroll
        for (int j = 0; j < 4; j++) vcur[j] = vnxt[j];
    }

    // ---- epilogue with the reference's (H,B)->(B,T,H*dh) view permutation ----
    const int b2 = bh & 1, h2 = bh >> 1;
    const float inv0 = 1.f / l0r, inv1 = 1.f / l1r;
    const int t0 = qb + qr + g, t1 = t0 + 8;
#pragma unroll
    for (int ni = 0; ni < 8; ni++) {
        const int col = h2 * D_HEAD + ni * 8 + 2 * l;
        float2 v;
        v.x = oa[ni][0] * inv0; v.y = oa[ni][1] * inv0;
        *(float2*)&g_ov[(size_t)(b2 * T_ + t0) * D_MODEL + col] = v;
        v.x = oa[ni][2] * inv1; v.y = oa[ni][3] * inv1;
        *(float2*)&g_ov[(size_t)(b2 * T_ + t1) * D_MODEL + col] = v;
    }
}

// ---------------- LayerNorm per row (residual already in g_y) ----------------
__global__ __launch_bounds__(256) void ln_kernel(const float* __restrict__ gamma,
                                                 const float* __restrict__ beta,
                                                 float* __restrict__ out) {
    __shared__ float red[8];
    const int row = blockIdx.x;
    const int tid = threadIdx.x;
    const float* yrow = g_y + (size_t)row * D_MODEL;

    float4 x = *(const float4*)(yrow + tid * 4);
    float s = x.x + x.y + x.z + x.w;
#pragma unroll
    for (int o = 16; o; o >>= 1) s += __shfl_xor_sync(0xffffffffu, s, o);
    if ((tid & 31) == 0) red[tid >> 5] = s;
    __syncthreads();
    s = red[0] + red[1] + red[2] + red[3] + red[4] + red[5] + red[6] + red[7];
    const float mu = s * (1.0f / D_MODEL);

    const float d0 = x.x - mu, d1 = x.y - mu, d2 = x.z - mu, d3 = x.w - mu;
    float v = d0 * d0 + d1 * d1 + d2 * d2 + d3 * d3;
#pragma unroll
    for (int o = 16; o; o >>= 1) v += __shfl_xor_sync(0xffffffffu, v, o);
    __syncthreads();
    if ((tid & 31) == 0) red[tid >> 5] = v;
    __syncthreads();
    v = red[0] + red[1] + red[2] + red[3] + red[4] + red[5] + red[6] + red[7];
    const float rstd = rsqrtf(v * (1.0f / D_MODEL) + 1e-5f);

    float4 gm = *(const float4*)(gamma + tid * 4);
    float4 bt = *(const float4*)(beta + tid * 4);
    float4 o4;
    o4.x = d0 * rstd * gm.x + bt.x;
    o4.y = d1 * rstd * gm.y + bt.y;
    o4.z = d2 * rstd * gm.z + bt.z;
    o4.w = d3 * rstd * gm.w + bt.w;
    *(float4*)(out + (size_t)row * D_MODEL + tid * 4) = o4;
}

// -----------------------------------------------------------------------------
extern "C" void kernel_launch(void* const* d_in, const int* in_sizes, int n_in,
                              void* d_out, int out_size) {
    const float* inp   = (const float*)d_in[0];
    const float* W_qkv = (const float*)d_in[1];
    const float* b_qkv = (const float*)d_in[2];
    const float* W_o   = (const float*)d_in[3];
    const float* gamma = (const float*)d_in[4];
    const float* beta  = (const float*)d_in[5];
    float* out = (float*)d_out;

    cudaFuncSetAttribute(qkv_gemm, cudaFuncAttributeMaxDynamicSharedMemorySize, GEMM_SMEM);
    cudaFuncSetAttribute(o_gemm,   cudaFuncAttributeMaxDynamicSharedMemorySize, GEMM_SMEM);
    cudaFuncSetAttribute(attn_kernel, cudaFuncAttributeMaxDynamicSharedMemorySize, ATT_SMEM);

    qkv_gemm<<<dim3(N_QKV / 128, M_TOK / 128), 256, GEMM_SMEM>>>(inp, W_qkv, b_qkv);
    attn_kernel<<<dim3(T_ / 128, B_ * N_HEAD), 256, ATT_SMEM>>>();
    o_gemm<<<dim3(D_MODEL / 128, M_TOK / 128), 256, GEMM_SMEM>>>(W_o, inp);
    ln_kernel<<<M_TOK, 256>>>(gamma, beta, out);
}

// round 7
// speedup vs baseline: 1.0723x; 1.0723x over previous
#include <cuda_runtime.h>
#include <math.h>

#define D_MODEL 1024
#define N_HEAD  16
#define D_HEAD  64
#define B_      2
#define T_      2048
#define M_TOK   (B_ * T_)              // 4096
#define N_QKV   (3 * N_HEAD * D_HEAD)  // 3072

// ---------------- scratch (device globals; no allocation allowed) ------------
__device__ unsigned g_inp_t[M_TOK * D_MODEL];      // inp as tf32 bits
__device__ unsigned g_wqkv_t[N_QKV * D_MODEL];     // W_qkv as tf32 bits
__device__ unsigned g_wo_t[D_MODEL * D_MODEL];     // W_o as tf32 bits
__device__ unsigned g_q[B_ * N_HEAD * T_ * D_HEAD]; // (B,H,T,dh) tf32 bits, pre-scaled
__device__ unsigned g_k[B_ * N_HEAD * T_ * D_HEAD]; // tf32 bits
__device__ unsigned g_v[B_ * N_HEAD * T_ * D_HEAD]; // tf32 bits
__device__ unsigned g_ov[M_TOK * D_MODEL];          // attn_vec tf32 bits (B,T,H*dh)
__device__ float    g_y[M_TOK * D_MODEL];           // inp + attn_out (fp32)

// ---------------- helpers ----------------------------------------------------
__device__ __forceinline__ unsigned f2t(float x) {
    unsigned u;
    asm("cvt.rna.tf32.f32 %0, %1;" : "=r"(u) : "f"(x));
    return u;
}

__device__ __forceinline__ void mma8(float* c,
                                     unsigned a0, unsigned a1, unsigned a2, unsigned a3,
                                     unsigned b0, unsigned b1) {
    asm volatile(
        "mma.sync.aligned.m16n8k8.row.col.f32.tf32.tf32.f32 "
        "{%0,%1,%2,%3}, {%4,%5,%6,%7}, {%8,%9}, {%0,%1,%2,%3};\n"
        : "+f"(c[0]), "+f"(c[1]), "+f"(c[2]), "+f"(c[3])
        : "r"(a0), "r"(a1), "r"(a2), "r"(a3), "r"(b0), "r"(b1));
}

__device__ __forceinline__ void cp16(unsigned* dst_smem, const unsigned* src) {
    unsigned d = (unsigned)__cvta_generic_to_shared(dst_smem);
    asm volatile(
        "{ .reg .u64 gp; cvta.to.global.u64 gp, %1;"
        "  cp.async.cg.shared.global [%0], [gp], 16; }\n"
        :: "r"(d), "l"(src) : "memory");
}
#define CP_COMMIT asm volatile("cp.async.commit_group;\n" ::: "memory")
#define CP_WAIT0  asm volatile("cp.async.wait_group 0;\n" ::: "memory")

// ---------------- one-shot fp32 -> tf32-bits convert -------------------------
__global__ __launch_bounds__(256) void cvt_kernel(const float4* __restrict__ src,
                                                  uint4* __restrict__ dst, int n4) {
    const int i = blockIdx.x * 256 + threadIdx.x;
    if (i < n4) {
        float4 v = src[i];
        uint4 u; u.x = f2t(v.x); u.y = f2t(v.y); u.z = f2t(v.z); u.w = f2t(v.w);
        dst[i] = u;
    }
}

// =============================================================================
// GEMMs: block 128x128, 8 warps (2m x 4n), warp 64x32 (4x4 atoms), k-step 32,
// cp.async double-buffered, tf32 bits in smem (pre-converted, no cvt in loop).
// =============================================================================
#define GP 36
#define GEMM_SMEM (2 * 2 * 128 * GP * 4)   // 73728 B

__global__ __launch_bounds__(256) void qkv_gemm(const float* __restrict__ bias) {
    extern __shared__ unsigned gsm[];
    unsigned* Asb = gsm;                    // [2][128][GP]
    unsigned* Bsb = gsm + 2 * 128 * GP;
    const int tid = threadIdx.x;
    const int m0 = blockIdx.y * 128, n0 = blockIdx.x * 128;
    const int w = tid >> 5, lane = tid & 31;
    const int g = lane >> 2, l = lane & 3;
    const int wm = (w >> 2) * 64, wn = (w & 3) * 32;

    float acc[4][4][4];
#pragma unroll
    for (int mi = 0; mi < 4; mi++)
#pragma unroll
        for (int ni = 0; ni < 4; ni++)
#pragma unroll
            for (int c = 0; c < 4; c++) acc[mi][ni][c] = 0.f;

    {
#pragma unroll
        for (int s4 = 0; s4 < 4; s4++) {
            const int idx = tid + s4 * 256;
            const int r = idx >> 3, c = (idx & 7) * 4;
            cp16(Asb + r * GP + c, g_inp_t + (size_t)(m0 + r) * D_MODEL + c);
            cp16(Bsb + r * GP + c, g_wqkv_t + (size_t)(n0 + r) * D_MODEL + c);
        }
        CP_COMMIT;
    }

    for (int kt = 0; kt < 32; kt++) {
        CP_WAIT0;
        __syncthreads();
        if (kt < 31) {
            const int ko = (kt + 1) * 32;
            unsigned* Ad = Asb + ((kt + 1) & 1) * 128 * GP;
            unsigned* Bd = Bsb + ((kt + 1) & 1) * 128 * GP;
#pragma unroll
            for (int s4 = 0; s4 < 4; s4++) {
                const int idx = tid + s4 * 256;
                const int r = idx >> 3, c = (idx & 7) * 4;
                cp16(Ad + r * GP + c, g_inp_t + (size_t)(m0 + r) * D_MODEL + ko + c);
                cp16(Bd + r * GP + c, g_wqkv_t + (size_t)(n0 + r) * D_MODEL + ko + c);
            }
            CP_COMMIT;
        }
        const unsigned* As = Asb + (kt & 1) * 128 * GP;
        const unsigned* Bs = Bsb + (kt & 1) * 128 * GP;
#pragma unroll
        for (int ka = 0; ka < 4; ka++) {
            const int kk = ka * 8;
            unsigned af[4][4], bf[4][2];
#pragma unroll
            for (int mi = 0; mi < 4; mi++) {
                const int r = wm + mi * 16 + g;
                af[mi][0] = As[r * GP + kk + l];
                af[mi][1] = As[(r + 8) * GP + kk + l];
                af[mi][2] = As[r * GP + kk + l + 4];
                af[mi][3] = As[(r + 8) * GP + kk + l + 4];
            }
#pragma unroll
            for (int ni = 0; ni < 4; ni++) {
                const int c = wn + ni * 8 + g;
                bf[ni][0] = Bs[c * GP + kk + l];
                bf[ni][1] = Bs[c * GP + kk + l + 4];
            }
#pragma unroll
            for (int mi = 0; mi < 4; mi++)
#pragma unroll
                for (int ni = 0; ni < 4; ni++)
                    mma8(acc[mi][ni], af[mi][0], af[mi][1], af[mi][2], af[mi][3],
                         bf[ni][0], bf[ni][1]);
        }
    }

    // epilogue: +bias, tf32-convert, scatter into (B,H,T,dh) q/k/v
    // q pre-scaled by 1/sqrt(dh) = 0.125
#pragma unroll
    for (int mi = 0; mi < 4; mi++) {
#pragma unroll
        for (int rs_ = 0; rs_ < 2; rs_++) {
            const int mm = m0 + wm + mi * 16 + g + rs_ * 8;
            const int b = mm >> 11, t = mm & (T_ - 1);
#pragma unroll
            for (int ni = 0; ni < 4; ni++) {
                const int o = n0 + wn + ni * 8 + 2 * l;
                float2 bb = *(const float2*)(bias + o);
                const float vx = acc[mi][ni][rs_ * 2]     + bb.x;
                const float vy = acc[mi][ni][rs_ * 2 + 1] + bb.y;
                const int part = o >> 10, rem = o & 1023;
                const int h = rem >> 6, d = rem & 63;
                const size_t idx = ((size_t)(b * N_HEAD + h) * T_ + t) * D_HEAD + d;
                uint2 u;
                if (part == 0) {
                    u.x = f2t(vx * 0.125f); u.y = f2t(vy * 0.125f);
                    *(uint2*)&g_q[idx] = u;
                } else if (part == 1) {
                    u.x = f2t(vx); u.y = f2t(vy);
                    *(uint2*)&g_k[idx] = u;
                } else {
                    u.x = f2t(vx); u.y = f2t(vy);
                    *(uint2*)&g_v[idx] = u;
                }
            }
        }
    }
}

__global__ __launch_bounds__(256) void o_gemm(const float* __restrict__ inp) {
    extern __shared__ unsigned gsm[];
    unsigned* Asb = gsm;
    unsigned* Bsb = gsm + 2 * 128 * GP;
    const int tid = threadIdx.x;
    const int m0 = blockIdx.y * 128, n0 = blockIdx.x * 128;
    const int w = tid >> 5, lane = tid & 31;
    const int g = lane >> 2, l = lane & 3;
    const int wm = (w >> 2) * 64, wn = (w & 3) * 32;

    float acc[4][4][4];
#pragma unroll
    for (int mi = 0; mi < 4; mi++)
#pragma unroll
        for (int ni = 0; ni < 4; ni++)
#pragma unroll
            for (int c = 0; c < 4; c++) acc[mi][ni][c] = 0.f;

    {
#pragma unroll
        for (int s4 = 0; s4 < 4; s4++) {
            const int idx = tid + s4 * 256;
            const int r = idx >> 3, c = (idx & 7) * 4;
            cp16(Asb + r * GP + c, g_ov + (size_t)(m0 + r) * D_MODEL + c);
            cp16(Bsb + r * GP + c, g_wo_t + (size_t)(n0 + r) * D_MODEL + c);
        }
        CP_COMMIT;
    }

    for (int kt = 0; kt < 32; kt++) {
        CP_WAIT0;
        __syncthreads();
        if (kt < 31) {
            const int ko = (kt + 1) * 32;
            unsigned* Ad = Asb + ((kt + 1) & 1) * 128 * GP;
            unsigned* Bd = Bsb + ((kt + 1) & 1) * 128 * GP;
#pragma unroll
            for (int s4 = 0; s4 < 4; s4++) {
                const int idx = tid + s4 * 256;
                const int r = idx >> 3, c = (idx & 7) * 4;
                cp16(Ad + r * GP + c, g_ov + (size_t)(m0 + r) * D_MODEL + ko + c);
                cp16(Bd + r * GP + c, g_wo_t + (size_t)(n0 + r) * D_MODEL + ko + c);
            }
            CP_COMMIT;
        }
        const unsigned* As = Asb + (kt & 1) * 128 * GP;
        const unsigned* Bs = Bsb + (kt & 1) * 128 * GP;
#pragma unroll
        for (int ka = 0; ka < 4; ka++) {
            const int kk = ka * 8;
            unsigned af[4][4], bf[4][2];
#pragma unroll
            for (int mi = 0; mi < 4; mi++) {
                const int r = wm + mi * 16 + g;
                af[mi][0] = As[r * GP + kk + l];
                af[mi][1] = As[(r + 8) * GP + kk + l];
                af[mi][2] = As[r * GP + kk + l + 4];
                af[mi][3] = As[(r + 8) * GP + kk + l + 4];
            }
#pragma unroll
            for (int ni = 0; ni < 4; ni++) {
                const int c = wn + ni * 8 + g;
                bf[ni][0] = Bs[c * GP + kk + l];
                bf[ni][1] = Bs[c * GP + kk + l + 4];
            }
#pragma unroll
            for (int mi = 0; mi < 4; mi++)
#pragma unroll
                for (int ni = 0; ni < 4; ni++)
                    mma8(acc[mi][ni], af[mi][0], af[mi][1], af[mi][2], af[mi][3],
                         bf[ni][0], bf[ni][1]);
        }
    }

#pragma unroll
    for (int mi = 0; mi < 4; mi++) {
#pragma unroll
        for (int rs_ = 0; rs_ < 2; rs_++) {
            const int mm = m0 + wm + mi * 16 + g + rs_ * 8;
#pragma unroll
            for (int ni = 0; ni < 4; ni++) {
                const int o = n0 + wn + ni * 8 + 2 * l;
                const size_t idx = (size_t)mm * D_MODEL + o;
                float2 r2 = *(const float2*)(inp + idx);
                float2 v;
                v.x = acc[mi][ni][rs_ * 2]     + r2.x;
                v.y = acc[mi][ni][rs_ * 2 + 1] + r2.y;
                *(float2*)&g_y[idx] = v;
            }
        }
    }
}

// =============================================================================
// Flash attention (R5 structure): Q block 128, key block 64, 8 warps (4m x 2n),
// warp tile 32x32. All inputs pre-converted tf32 bits -> pure copies; only the
// exp() output P needs a tf32 convert.
// =============================================================================
#define AP 68
#define SMEM_ATTN ((size_t)((128 + 64 + 64 + 128) * AP + 256 + 3 * 128) * 4)

__global__ __launch_bounds__(256) void attn_kernel() {
    extern __shared__ unsigned smb[];
    unsigned* Qs = smb;                       // [128][AP]
    unsigned* Ks = Qs + 128 * AP;             // [64][AP]   (t, d)
    unsigned* Vs = Ks + 64 * AP;              // [64][AP]   (d, t) transposed
    unsigned* Ps = Vs + 64 * AP;              // [128][AP]  (q, t)
    float* f_red = (float*)(Ps + 128 * AP);   // [2][128]
    float* f_m  = f_red + 256;                // [128]
    float* f_l  = f_m + 128;                  // [128]
    float* f_al = f_l + 128;                  // [128]

    const int bh = blockIdx.y;
    const int qb = blockIdx.x * 128;
    const unsigned* Qg = g_q + (size_t)bh * T_ * D_HEAD;
    const unsigned* Kg = g_k + (size_t)bh * T_ * D_HEAD;
    const unsigned* Vg = g_v + (size_t)bh * T_ * D_HEAD;

    const int tid = threadIdx.x;
    const int w = tid >> 5, lane = tid & 31;
    const int g = lane >> 2, l = lane & 3;
    const int wm = (w >> 1) * 32;
    const int nwi = w & 1;
    const int wn = nwi * 32;

    if (tid < 128) { f_m[tid] = -1e30f; f_l[tid] = 0.f; }

    // load Q (128x64) — pre-scaled tf32 bits, plain copy
#pragma unroll
    for (int it = 0; it < 8; it++) {
        const int fi = tid + it * 256;
        const int r = fi >> 4, c = (fi & 15) * 4;
        *(uint4*)&Qs[r * AP + c] = *(const uint4*)(Qg + (size_t)(qb + r) * D_HEAD + c);
    }

    float oa[2][4][4];
#pragma unroll
    for (int mi = 0; mi < 2; mi++)
#pragma unroll
        for (int ni = 0; ni < 4; ni++)
#pragma unroll
            for (int c = 0; c < 4; c++) oa[mi][ni][c] = 0.f;

    for (int kb = 0; kb < T_; kb += 64) {
        __syncthreads();
        // K tile (64x64) plain copy
#pragma unroll
        for (int it = 0; it < 4; it++) {
            const int fi = tid + it * 256;
            const int r = fi >> 4, c = (fi & 15) * 4;
            *(uint4*)&Ks[r * AP + c] = *(const uint4*)(Kg + (size_t)(kb + r) * D_HEAD + c);
        }
        // V tile transposed -> [d][t]
        {
            const int r = tid & 63, cb = (tid >> 6) * 16;
#pragma unroll
            for (int c4 = 0; c4 < 4; c4++) {
                uint4 v4 = *(const uint4*)(Vg + (size_t)(kb + r) * D_HEAD + cb + c4 * 4);
                const int d = cb + c4 * 4;
                Vs[(d + 0) * AP + r] = v4.x;
                Vs[(d + 1) * AP + r] = v4.y;
                Vs[(d + 2) * AP + r] = v4.z;
                Vs[(d + 3) * AP + r] = v4.w;
            }
        }
        __syncthreads();

        // S = Q @ K^T
        float s[2][4][4];
#pragma unroll
        for (int mi = 0; mi < 2; mi++)
#pragma unroll
            for (int ni = 0; ni < 4; ni++)
#pragma unroll
                for (int c = 0; c < 4; c++) s[mi][ni][c] = 0.f;

#pragma unroll
        for (int ka = 0; ka < 8; ka++) {
            const int kk = ka * 8;
            unsigned qf[2][4], kf[4][2];
#pragma unroll
            for (int mi = 0; mi < 2; mi++) {
                const int r = wm + mi * 16 + g;
                qf[mi][0] = Qs[r * AP + kk + l];       qf[mi][1] = Qs[(r + 8) * AP + kk + l];
                qf[mi][2] = Qs[r * AP + kk + l + 4];   qf[mi][3] = Qs[(r + 8) * AP + kk + l + 4];
            }
#pragma unroll
            for (int ni = 0; ni < 4; ni++) {
                const int c = wn + ni * 8 + g;
                kf[ni][0] = Ks[c * AP + kk + l]; kf[ni][1] = Ks[c * AP + kk + l + 4];
            }
#pragma unroll
            for (int mi = 0; mi < 2; mi++)
#pragma unroll
                for (int ni = 0; ni < 4; ni++)
                    mma8(s[mi][ni], qf[mi][0], qf[mi][1], qf[mi][2], qf[mi][3],
                         kf[ni][0], kf[ni][1]);
        }

        // partial row max (per warp over its 32 cols)
#pragma unroll
        for (int mi = 0; mi < 2; mi++)
#pragma unroll
            for (int rs_ = 0; rs_ < 2; rs_++) {
                const int row = wm + mi * 16 + rs_ * 8 + g;
                float mx = s[mi][0][rs_ * 2];
#pragma unroll
                for (int ni = 0; ni < 4; ni++) {
                    mx = fmaxf(mx, s[mi][ni][rs_ * 2]);
                    mx = fmaxf(mx, s[mi][ni][rs_ * 2 + 1]);
                }
                mx = fmaxf(mx, __shfl_xor_sync(0xffffffffu, mx, 1));
                mx = fmaxf(mx, __shfl_xor_sync(0xffffffffu, mx, 2));
                if (l == 0) f_red[nwi * 128 + row] = mx;
            }
        __syncthreads();
        if (tid < 128) {
            const float mx = fmaxf(f_red[tid], f_red[128 + tid]);
            const float mo = f_m[tid];
            const float mn = fmaxf(mo, mx);
            f_al[tid] = __expf(mo - mn);
            f_m[tid] = mn;
        }
        __syncthreads();

        // exp, write P (tf32 bits), partial row sums
#pragma unroll
        for (int mi = 0; mi < 2; mi++)
#pragma unroll
            for (int rs_ = 0; rs_ < 2; rs_++) {
                const int row = wm + mi * 16 + rs_ * 8 + g;
                const float mn = f_m[row];
                float rsum = 0.f;
#pragma unroll
                for (int ni = 0; ni < 4; ni++) {
                    const float p0 = __expf(s[mi][ni][rs_ * 2]     - mn);
                    const float p1 = __expf(s[mi][ni][rs_ * 2 + 1] - mn);
                    rsum += p0 + p1;
                    uint2 u; u.x = f2t(p0); u.y = f2t(p1);
                    *(uint2*)&Ps[row * AP + wn + ni * 8 + 2 * l] = u;
                }
                rsum += __shfl_xor_sync(0xffffffffu, rsum, 1);
                rsum += __shfl_xor_sync(0xffffffffu, rsum, 2);
                if (l == 0) f_red[nwi * 128 + row] = rsum;
            }
        __syncthreads();
        if (tid < 128)
            f_l[tid] = f_l[tid] * f_al[tid] + f_red[tid] + f_red[128 + tid];

        // rescale O accumulators
#pragma unroll
        for (int mi = 0; mi < 2; mi++)
#pragma unroll
            for (int rs_ = 0; rs_ < 2; rs_++) {
                const int row = wm + mi * 16 + rs_ * 8 + g;
                const float al = f_al[row];
#pragma unroll
                for (int ni = 0; ni < 4; ni++) {
                    oa[mi][ni][rs_ * 2]     *= al;
                    oa[mi][ni][rs_ * 2 + 1] *= al;
                }
            }

        // O += P @ V
#pragma unroll
        for (int ka = 0; ka < 8; ka++) {
            const int kk = ka * 8;
            unsigned pf[2][4], vf[4][2];
#pragma unroll
            for (int mi = 0; mi < 2; mi++) {
                const int r = wm + mi * 16 + g;
                pf[mi][0] = Ps[r * AP + kk + l];       pf[mi][1] = Ps[(r + 8) * AP + kk + l];
                pf[mi][2] = Ps[r * AP + kk + l + 4];   pf[mi][3] = Ps[(r + 8) * AP + kk + l + 4];
            }
#pragma unroll
            for (int ni = 0; ni < 4; ni++) {
                const int d = wn + ni * 8 + g;
                vf[ni][0] = Vs[d * AP + kk + l]; vf[ni][1] = Vs[d * AP + kk + l + 4];
            }
#pragma unroll
            for (int mi = 0; mi < 2; mi++)
#pragma unroll
                for (int ni = 0; ni < 4; ni++)
                    mma8(oa[mi][ni], pf[mi][0], pf[mi][1], pf[mi][2], pf[mi][3],
                         vf[ni][0], vf[ni][1]);
        }
    }
    __syncthreads();

    // epilogue with the reference's (H,B)->(B,T,H*dh) view permutation
    // (g_ov stored as tf32 bits for o_gemm)
    const int b2 = bh & 1, h2 = bh >> 1;
#pragma unroll
    for (int mi = 0; mi < 2; mi++)
#pragma unroll
        for (int rs_ = 0; rs_ < 2; rs_++) {
            const int row = wm + mi * 16 + rs_ * 8 + g;
            const float inv = 1.f / f_l[row];
            const int t = qb + row;
#pragma unroll
            for (int ni = 0; ni < 4; ni++) {
                const int col = h2 * D_HEAD + wn + ni * 8 + 2 * l;
                uint2 u;
                u.x = f2t(oa[mi][ni][rs_ * 2]     * inv);
                u.y = f2t(oa[mi][ni][rs_ * 2 + 1] * inv);
                *(uint2*)&g_ov[(size_t)(b2 * T_ + t) * D_MODEL + col] = u;
            }
        }
}

// ---------------- LayerNorm per row (residual already in g_y) ----------------
__global__ __launch_bounds__(256) void ln_kernel(const float* __restrict__ gamma,
                                                 const float* __restrict__ beta,
                                                 float* __restrict__ out) {
    __shared__ float red[8];
    const int row = blockIdx.x;
    const int tid = threadIdx.x;
    const float* yrow = g_y + (size_t)row * D_MODEL;

    float4 x = *(const float4*)(yrow + tid * 4);
    float s = x.x + x.y + x.z + x.w;
#pragma unroll
    for (int o = 16; o; o >>= 1) s += __shfl_xor_sync(0xffffffffu, s, o);
    if ((tid & 31) == 0) red[tid >> 5] = s;
    __syncthreads();
    s = red[0] + red[1] + red[2] + red[3] + red[4] + red[5] + red[6] + red[7];
    const float mu = s * (1.0f / D_MODEL);

    const float d0 = x.x - mu, d1 = x.y - mu, d2 = x.z - mu, d3 = x.w - mu;
    float v = d0 * d0 + d1 * d1 + d2 * d2 + d3 * d3;
#pragma unroll
    for (int o = 16; o; o >>= 1) v += __shfl_xor_sync(0xffffffffu, v, o);
    __syncthreads();
    if ((tid & 31) == 0) red[tid >> 5] = v;
    __syncthreads();
    v = red[0] + red[1] + red[2] + red[3] + red[4] + red[5] + red[6] + red[7];
    const float rstd = rsqrtf(v * (1.0f / D_MODEL) + 1e-5f);

    float4 gm = *(const float4*)(gamma + tid * 4);
    float4 bt = *(const float4*)(beta + tid * 4);
    float4 o4;
    o4.x = d0 * rstd * gm.x + bt.x;
    o4.y = d1 * rstd * gm.y + bt.y;
    o4.z = d2 * rstd * gm.z + bt.z;
    o4.w = d3 * rstd * gm.w + bt.w;
    *(float4*)(out + (size_t)row * D_MODEL + tid * 4) = o4;
}

// -----------------------------------------------------------------------------
extern "C" void kernel_launch(void* const* d_in, const int* in_sizes, int n_in,
                              void* d_out, int out_size) {
    const float* inp   = (const float*)d_in[0];
    const float* W_qkv = (const float*)d_in[1];
    const float* b_qkv = (const float*)d_in[2];
    const float* W_o   = (const float*)d_in[3];
    const float* gamma = (const float*)d_in[4];
    const float* beta  = (const float*)d_in[5];
    float* out = (float*)d_out;

    cudaFuncSetAttribute(qkv_gemm, cudaFuncAttributeMaxDynamicSharedMemorySize, GEMM_SMEM);
    cudaFuncSetAttribute(o_gemm,   cudaFuncAttributeMaxDynamicSharedMemorySize, GEMM_SMEM);
    cudaFuncSetAttribute(attn_kernel, cudaFuncAttributeMaxDynamicSharedMemorySize, (int)SMEM_ATTN);

    unsigned* d_inp_t;  cudaGetSymbolAddress((void**)&d_inp_t,  g_inp_t);
    unsigned* d_wqkv_t; cudaGetSymbolAddress((void**)&d_wqkv_t, g_wqkv_t);
    unsigned* d_wo_t;   cudaGetSymbolAddress((void**)&d_wo_t,   g_wo_t);

    // pre-convert fp32 -> tf32 bits (once per launch; memory-bound, ~25us)
    cvt_kernel<<<(M_TOK * D_MODEL / 4 + 255) / 256, 256>>>(
        (const float4*)inp, (uint4*)d_inp_t, M_TOK * D_MODEL / 4);
    cvt_kernel<<<(N_QKV * D_MODEL / 4 + 255) / 256, 256>>>(
        (const float4*)W_qkv, (uint4*)d_wqkv_t, N_QKV * D_MODEL / 4);
    cvt_kernel<<<(D_MODEL * D_MODEL / 4 + 255) / 256, 256>>>(
        (const float4*)W_o, (uint4*)d_wo_t, D_MODEL * D_MODEL / 4);

    qkv_gemm<<<dim3(N_QKV / 128, M_TOK / 128), 256, GEMM_SMEM>>>(b_qkv);
    attn_kernel<<<dim3(T_ / 128, B_ * N_HEAD), 256, SMEM_ATTN>>>();
    o_gemm<<<dim3(D_MODEL / 128, M_TOK / 128), 256, GEMM_SMEM>>>(inp);
    ln_kernel<<<M_TOK, 256>>>(gamma, beta, out);
}

// round 8
// speedup vs baseline: 1.2921x; 1.2050x over previous
#include <cuda_runtime.h>
#include <math.h>

#define D_MODEL 1024
#define N_HEAD  16
#define D_HEAD  64
#define B_      2
#define T_      2048
#define M_TOK   (B_ * T_)              // 4096
#define N_QKV   (3 * N_HEAD * D_HEAD)  // 3072

// ---------------- scratch (device globals; no allocation allowed) ------------
__device__ unsigned g_inp_t[M_TOK * D_MODEL];       // inp as tf32 bits
__device__ unsigned g_wqkv_t[N_QKV * D_MODEL];      // W_qkv as tf32 bits
__device__ unsigned g_wo_t[D_MODEL * D_MODEL];      // W_o as tf32 bits
__device__ unsigned g_q[B_ * N_HEAD * T_ * D_HEAD]; // (B,H,T,dh) tf32, pre-scaled by 0.125*log2e
__device__ unsigned g_k[B_ * N_HEAD * T_ * D_HEAD]; // (B,H,T,dh) tf32
__device__ unsigned g_vt[B_ * N_HEAD * D_HEAD * T_];// (B,H,dh,T) tf32  (V transposed)
__device__ unsigned g_ov[M_TOK * D_MODEL];          // attn_vec tf32 bits (B,T,H*dh)
__device__ float    g_y[M_TOK * D_MODEL];           // inp + attn_out (fp32)

// ---------------- helpers ----------------------------------------------------
__device__ __forceinline__ unsigned f2t(float x) {
    unsigned u;
    asm("cvt.rna.tf32.f32 %0, %1;" : "=r"(u) : "f"(x));
    return u;
}

__device__ __forceinline__ void mma8(float* c,
                                     unsigned a0, unsigned a1, unsigned a2, unsigned a3,
                                     unsigned b0, unsigned b1) {
    asm volatile(
        "mma.sync.aligned.m16n8k8.row.col.f32.tf32.tf32.f32 "
        "{%0,%1,%2,%3}, {%4,%5,%6,%7}, {%8,%9}, {%0,%1,%2,%3};\n"
        : "+f"(c[0]), "+f"(c[1]), "+f"(c[2]), "+f"(c[3])
        : "r"(a0), "r"(a1), "r"(a2), "r"(a3), "r"(b0), "r"(b1));
}

__device__ __forceinline__ void cp16(unsigned* dst_smem, const unsigned* src) {
    unsigned d = (unsigned)__cvta_generic_to_shared(dst_smem);
    asm volatile(
        "{ .reg .u64 gp; cvta.to.global.u64 gp, %1;"
        "  cp.async.cg.shared.global [%0], [gp], 16; }\n"
        :: "r"(d), "l"(src) : "memory");
}
#define CP_COMMIT asm volatile("cp.async.commit_group;\n" ::: "memory")
#define CP_WAIT0  asm volatile("cp.async.wait_group 0;\n" ::: "memory")

// ---------------- one-shot fp32 -> tf32-bits convert -------------------------
__global__ __launch_bounds__(256) void cvt_kernel(const float4* __restrict__ src,
                                                  uint4* __restrict__ dst, int n4) {
    const int i = blockIdx.x * 256 + threadIdx.x;
    if (i < n4) {
        float4 v = src[i];
        uint4 u; u.x = f2t(v.x); u.y = f2t(v.y); u.z = f2t(v.z); u.w = f2t(v.w);
        dst[i] = u;
    }
}

// =============================================================================
// GEMMs: block 128x128, 8 warps (2m x 4n), warp 64x32 (4x4 atoms), k-step 32,
// cp.async double-buffered, tf32 bits in smem.
// =============================================================================
#define GP 36
#define GEMM_SMEM (2 * 2 * 128 * GP * 4)   // 73728 B
#define QSCALE 0.18033688011112042f        // 0.125 * log2(e)

__global__ __launch_bounds__(256) void qkv_gemm(const float* __restrict__ bias) {
    extern __shared__ unsigned gsm[];
    unsigned* Asb = gsm;                    // [2][128][GP]
    unsigned* Bsb = gsm + 2 * 128 * GP;
    const int tid = threadIdx.x;
    const int m0 = blockIdx.y * 128, n0 = blockIdx.x * 128;
    const int w = tid >> 5, lane = tid & 31;
    const int g = lane >> 2, l = lane & 3;
    const int wm = (w >> 2) * 64, wn = (w & 3) * 32;

    float acc[4][4][4];
#pragma unroll
    for (int mi = 0; mi < 4; mi++)
#pragma unroll
        for (int ni = 0; ni < 4; ni++)
#pragma unroll
            for (int c = 0; c < 4; c++) acc[mi][ni][c] = 0.f;

    {
#pragma unroll
        for (int s4 = 0; s4 < 4; s4++) {
            const int idx = tid + s4 * 256;
            const int r = idx >> 3, c = (idx & 7) * 4;
            cp16(Asb + r * GP + c, g_inp_t + (size_t)(m0 + r) * D_MODEL + c);
            cp16(Bsb + r * GP + c, g_wqkv_t + (size_t)(n0 + r) * D_MODEL + c);
        }
        CP_COMMIT;
    }

    for (int kt = 0; kt < 32; kt++) {
        CP_WAIT0;
        __syncthreads();
        if (kt < 31) {
            const int ko = (kt + 1) * 32;
            unsigned* Ad = Asb + ((kt + 1) & 1) * 128 * GP;
            unsigned* Bd = Bsb + ((kt + 1) & 1) * 128 * GP;
#pragma unroll
            for (int s4 = 0; s4 < 4; s4++) {
                const int idx = tid + s4 * 256;
                const int r = idx >> 3, c = (idx & 7) * 4;
                cp16(Ad + r * GP + c, g_inp_t + (size_t)(m0 + r) * D_MODEL + ko + c);
                cp16(Bd + r * GP + c, g_wqkv_t + (size_t)(n0 + r) * D_MODEL + ko + c);
            }
            CP_COMMIT;
        }
        const unsigned* As = Asb + (kt & 1) * 128 * GP;
        const unsigned* Bs = Bsb + (kt & 1) * 128 * GP;
#pragma unroll
        for (int ka = 0; ka < 4; ka++) {
            const int kk = ka * 8;
            unsigned af[4][4], bf[4][2];
#pragma unroll
            for (int mi = 0; mi < 4; mi++) {
                const int r = wm + mi * 16 + g;
                af[mi][0] = As[r * GP + kk + l];
                af[mi][1] = As[(r + 8) * GP + kk + l];
                af[mi][2] = As[r * GP + kk + l + 4];
                af[mi][3] = As[(r + 8) * GP + kk + l + 4];
            }
#pragma unroll
            for (int ni = 0; ni < 4; ni++) {
                const int c = wn + ni * 8 + g;
                bf[ni][0] = Bs[c * GP + kk + l];
                bf[ni][1] = Bs[c * GP + kk + l + 4];
            }
#pragma unroll
            for (int mi = 0; mi < 4; mi++)
#pragma unroll
                for (int ni = 0; ni < 4; ni++)
                    mma8(acc[mi][ni], af[mi][0], af[mi][1], af[mi][2], af[mi][3],
                         bf[ni][0], bf[ni][1]);
        }
    }

    // epilogue: +bias, tf32-convert, scatter.
    // q pre-scaled by 0.125*log2e (exp2-domain softmax); v written TRANSPOSED.
#pragma unroll
    for (int mi = 0; mi < 4; mi++) {
#pragma unroll
        for (int rs_ = 0; rs_ < 2; rs_++) {
            const int mm = m0 + wm + mi * 16 + g + rs_ * 8;
            const int b = mm >> 11, t = mm & (T_ - 1);
#pragma unroll
            for (int ni = 0; ni < 4; ni++) {
                const int o = n0 + wn + ni * 8 + 2 * l;
                float2 bb = *(const float2*)(bias + o);
                const float vx = acc[mi][ni][rs_ * 2]     + bb.x;
                const float vy = acc[mi][ni][rs_ * 2 + 1] + bb.y;
                const int part = o >> 10, rem = o & 1023;
                const int h = rem >> 6, d = rem & 63;
                const size_t bhh = (size_t)(b * N_HEAD + h);
                if (part == 0) {
                    uint2 u; u.x = f2t(vx * QSCALE); u.y = f2t(vy * QSCALE);
                    *(uint2*)&g_q[(bhh * T_ + t) * D_HEAD + d] = u;
                } else if (part == 1) {
                    uint2 u; u.x = f2t(vx); u.y = f2t(vy);
                    *(uint2*)&g_k[(bhh * T_ + t) * D_HEAD + d] = u;
                } else {
                    g_vt[(bhh * D_HEAD + d)     * T_ + t] = f2t(vx);
                    g_vt[(bhh * D_HEAD + d + 1) * T_ + t] = f2t(vy);
                }
            }
        }
    }
}

__global__ __launch_bounds__(256) void o_gemm(const float* __restrict__ inp) {
    extern __shared__ unsigned gsm[];
    unsigned* Asb = gsm;
    unsigned* Bsb = gsm + 2 * 128 * GP;
    const int tid = threadIdx.x;
    const int m0 = blockIdx.y * 128, n0 = blockIdx.x * 128;
    const int w = tid >> 5, lane = tid & 31;
    const int g = lane >> 2, l = lane & 3;
    const int wm = (w >> 2) * 64, wn = (w & 3) * 32;

    float acc[4][4][4];
#pragma unroll
    for (int mi = 0; mi < 4; mi++)
#pragma unroll
        for (int ni = 0; ni < 4; ni++)
#pragma unroll
            for (int c = 0; c < 4; c++) acc[mi][ni][c] = 0.f;

    {
#pragma unroll
        for (int s4 = 0; s4 < 4; s4++) {
            const int idx = tid + s4 * 256;
            const int r = idx >> 3, c = (idx & 7) * 4;
            cp16(Asb + r * GP + c, g_ov + (size_t)(m0 + r) * D_MODEL + c);
            cp16(Bsb + r * GP + c, g_wo_t + (size_t)(n0 + r) * D_MODEL + c);
        }
        CP_COMMIT;
    }

    for (int kt = 0; kt < 32; kt++) {
        CP_WAIT0;
        __syncthreads();
        if (kt < 31) {
            const int ko = (kt + 1) * 32;
            unsigned* Ad = Asb + ((kt + 1) & 1) * 128 * GP;
            unsigned* Bd = Bsb + ((kt + 1) & 1) * 128 * GP;
#pragma unroll
            for (int s4 = 0; s4 < 4; s4++) {
                const int idx = tid + s4 * 256;
                const int r = idx >> 3, c = (idx & 7) * 4;
                cp16(Ad + r * GP + c, g_ov + (size_t)(m0 + r) * D_MODEL + ko + c);
                cp16(Bd + r * GP + c, g_wo_t + (size_t)(n0 + r) * D_MODEL + ko + c);
            }
            CP_COMMIT;
        }
        const unsigned* As = Asb + (kt & 1) * 128 * GP;
        const unsigned* Bs = Bsb + (kt & 1) * 128 * GP;
#pragma unroll
        for (int ka = 0; ka < 4; ka++) {
            const int kk = ka * 8;
            unsigned af[4][4], bf[4][2];
#pragma unroll
            for (int mi = 0; mi < 4; mi++) {
                const int r = wm + mi * 16 + g;
                af[mi][0] = As[r * GP + kk + l];
                af[mi][1] = As[(r + 8) * GP + kk + l];
                af[mi][2] = As[r * GP + kk + l + 4];
                af[mi][3] = As[(r + 8) * GP + kk + l + 4];
            }
#pragma unroll
            for (int ni = 0; ni < 4; ni++) {
                const int c = wn + ni * 8 + g;
                bf[ni][0] = Bs[c * GP + kk + l];
                bf[ni][1] = Bs[c * GP + kk + l + 4];
            }
#pragma unroll
            for (int mi = 0; mi < 4; mi++)
#pragma unroll
                for (int ni = 0; ni < 4; ni++)
                    mma8(acc[mi][ni], af[mi][0], af[mi][1], af[mi][2], af[mi][3],
                         bf[ni][0], bf[ni][1]);
        }
    }

#pragma unroll
    for (int mi = 0; mi < 4; mi++) {
#pragma unroll
        for (int rs_ = 0; rs_ < 2; rs_++) {
            const int mm = m0 + wm + mi * 16 + g + rs_ * 8;
#pragma unroll
            for (int ni = 0; ni < 4; ni++) {
                const int o = n0 + wn + ni * 8 + 2 * l;
                const size_t idx = (size_t)mm * D_MODEL + o;
                float2 r2 = *(const float2*)(inp + idx);
                float2 v;
                v.x = acc[mi][ni][rs_ * 2]     + r2.x;
                v.y = acc[mi][ni][rs_ * 2 + 1] + r2.y;
                *(float2*)&g_y[idx] = v;
            }
        }
    }
}

// =============================================================================
// Flash attention: 8 warps x 16 full query rows (QB=128, KB=64).
// Q fragments in registers; register-only softmax (exp2 domain);
// P C-frag -> A-frag via shuffles; K and Vt via cp.async double-buffer.
// One __syncthreads per key-iter. No STS in main loop.
// =============================================================================
#define AP 68
#define ATT_SMEM ((2 * 64 * AP + 2 * 64 * AP) * 4)   // 69632 B

__global__ __launch_bounds__(256) void attn_kernel() {
    extern __shared__ unsigned smb[];
    unsigned* Ksm = smb;                  // [2][64][AP]; also Q staging [128][AP]
    unsigned* Vsm = smb + 2 * 64 * AP;    // [2][64][AP]  Vt tiles [d][key]

    const int bh = blockIdx.y;
    const int qb = blockIdx.x * 128;
    const unsigned* Qg = g_q + (size_t)bh * T_ * D_HEAD;
    const unsigned* Kg = g_k + (size_t)bh * T_ * D_HEAD;
    const unsigned* Vt = g_vt + (size_t)bh * D_HEAD * T_;

    const int tid = threadIdx.x;
    const int w = tid >> 5, lane = tid & 31;
    const int g = lane >> 2, l = lane & 3;
    const int qr = w * 16;

    // ---- stage Q once, load fragments into registers ----
#pragma unroll
    for (int s4 = 0; s4 < 8; s4++) {
        const int idx = tid + s4 * 256;          // 128 rows x 16 chunks
        const int r = idx >> 4, c = (idx & 15) * 4;
        cp16(Ksm + r * AP + c, Qg + (size_t)(qb + r) * D_HEAD + c);
    }
    CP_COMMIT; CP_WAIT0;
    __syncthreads();

    unsigned qa[8][4];
#pragma unroll
    for (int ka = 0; ka < 8; ka++) {
        const int kk = ka * 8;
        qa[ka][0] = Ksm[(qr + g) * AP + kk + l];
        qa[ka][1] = Ksm[(qr + 8 + g) * AP + kk + l];
        qa[ka][2] = Ksm[(qr + g) * AP + kk + l + 4];
        qa[ka][3] = Ksm[(qr + 8 + g) * AP + kk + l + 4];
    }
    __syncthreads();   // Q reads done before K tile 0 overwrites staging

    // ---- prologue: tile 0 ----
#pragma unroll
    for (int s4 = 0; s4 < 4; s4++) {
        const int idx = tid + s4 * 256;          // 64 rows x 16 chunks
        const int r = idx >> 4, c = (idx & 15) * 4;
        cp16(Ksm + r * AP + c, Kg + (size_t)r * D_HEAD + c);
        cp16(Vsm + r * AP + c, Vt + (size_t)r * T_ + c);
    }
    CP_COMMIT;

    float oa[8][4];
#pragma unroll
    for (int ni = 0; ni < 8; ni++)
#pragma unroll
        for (int c = 0; c < 4; c++) oa[ni][c] = 0.f;
    float m0r = -1e30f, m1r = -1e30f, l0r = 0.f, l1r = 0.f;

    const int src0 = (lane & 28) | (l >> 1);
    const int src1 = src0 + 2;
    const bool odd = (l & 1);

    for (int it = 0; it < 32; it++) {
        CP_WAIT0;
        __syncthreads();
        if (it < 31) {
            const int kb2 = (it + 1) * 64;
            unsigned* Kd = Ksm + ((it + 1) & 1) * 64 * AP;
            unsigned* Vd = Vsm + ((it + 1) & 1) * 64 * AP;
#pragma unroll
            for (int s4 = 0; s4 < 4; s4++) {
                const int idx = tid + s4 * 256;
                const int r = idx >> 4, c = (idx & 15) * 4;
                cp16(Kd + r * AP + c, Kg + (size_t)(kb2 + r) * D_HEAD + c);
                cp16(Vd + r * AP + c, Vt + (size_t)r * T_ + kb2 + c);
            }
            CP_COMMIT;
        }
        const unsigned* Kb = Ksm + (it & 1) * 64 * AP;
        const unsigned* Vb = Vsm + (it & 1) * 64 * AP;

        // ---- S = Q @ K^T (16 rows x 64 keys per warp) ----
        float s[8][4];
#pragma unroll
        for (int ni = 0; ni < 8; ni++)
#pragma unroll
            for (int c = 0; c < 4; c++) s[ni][c] = 0.f;
#pragma unroll
        for (int ka = 0; ka < 8; ka++) {
            const int kk = ka * 8;
            unsigned kf0[8], kf1[8];
#pragma unroll
            for (int ni = 0; ni < 8; ni++) {
                const int c = ni * 8 + g;
                kf0[ni] = Kb[c * AP + kk + l];
                kf1[ni] = Kb[c * AP + kk + l + 4];
            }
#pragma unroll
            for (int ni = 0; ni < 8; ni++)
                mma8(s[ni], qa[ka][0], qa[ka][1], qa[ka][2], qa[ka][3],
                     kf0[ni], kf1[ni]);
        }

        // ---- register softmax (exp2 domain; rows g and g+8) ----
        float mx0 = -1e30f, mx1 = -1e30f;
#pragma unroll
        for (int ni = 0; ni < 8; ni++) {
            mx0 = fmaxf(mx0, fmaxf(s[ni][0], s[ni][1]));
            mx1 = fmaxf(mx1, fmaxf(s[ni][2], s[ni][3]));
        }
        mx0 = fmaxf(mx0, __shfl_xor_sync(0xffffffffu, mx0, 1, 4));
        mx0 = fmaxf(mx0, __shfl_xor_sync(0xffffffffu, mx0, 2, 4));
        mx1 = fmaxf(mx1, __shfl_xor_sync(0xffffffffu, mx1, 1, 4));
        mx1 = fmaxf(mx1, __shfl_xor_sync(0xffffffffu, mx1, 2, 4));
        const float mn0 = fmaxf(m0r, mx0), mn1 = fmaxf(m1r, mx1);
        const float al0 = exp2f(m0r - mn0), al1 = exp2f(m1r - mn1);
        m0r = mn0; m1r = mn1;
        float rs0 = 0.f, rs1 = 0.f;
#pragma unroll
        for (int ni = 0; ni < 8; ni++) {
            s[ni][0] = exp2f(s[ni][0] - mn0);
            s[ni][1] = exp2f(s[ni][1] - mn0);
            s[ni][2] = exp2f(s[ni][2] - mn1);
            s[ni][3] = exp2f(s[ni][3] - mn1);
            rs0 += s[ni][0] + s[ni][1];
            rs1 += s[ni][2] + s[ni][3];
        }
        rs0 += __shfl_xor_sync(0xffffffffu, rs0, 1, 4);
        rs0 += __shfl_xor_sync(0xffffffffu, rs0, 2, 4);
        rs1 += __shfl_xor_sync(0xffffffffu, rs1, 1, 4);
        rs1 += __shfl_xor_sync(0xffffffffu, rs1, 2, 4);
        l0r = l0r * al0 + rs0;
        l1r = l1r * al1 + rs1;
#pragma unroll
        for (int ni = 0; ni < 8; ni++) {
            oa[ni][0] *= al0; oa[ni][1] *= al0;
            oa[ni][2] *= al1; oa[ni][3] *= al1;
        }

        // cvt P to tf32 in place
#pragma unroll
        for (int ni = 0; ni < 8; ni++)
#pragma unroll
            for (int c = 0; c < 4; c++)
                s[ni][c] = __uint_as_float(f2t(s[ni][c]));

        // ---- O += P @ V : shuffle C-frag -> A-frag per 8-key block ----
#pragma unroll
        for (int ka = 0; ka < 8; ka++) {
            const float t00 = __shfl_sync(0xffffffffu, s[ka][0], src0);
            const float t01 = __shfl_sync(0xffffffffu, s[ka][1], src0);
            const float t20 = __shfl_sync(0xffffffffu, s[ka][2], src0);
            const float t21 = __shfl_sync(0xffffffffu, s[ka][3], src0);
            const float u00 = __shfl_sync(0xffffffffu, s[ka][0], src1);
            const float u01 = __shfl_sync(0xffffffffu, s[ka][1], src1);
            const float u20 = __shfl_sync(0xffffffffu, s[ka][2], src1);
            const float u21 = __shfl_sync(0xffffffffu, s[ka][3], src1);
            const unsigned pa0 = __float_as_uint(odd ? t01 : t00);
            const unsigned pa1 = __float_as_uint(odd ? t21 : t20);
            const unsigned pa2 = __float_as_uint(odd ? u01 : u00);
            const unsigned pa3 = __float_as_uint(odd ? u21 : u20);
            const int kk = ka * 8;
            unsigned vf0[8], vf1[8];
#pragma unroll
            for (int ni = 0; ni < 8; ni++) {
                const int d = ni * 8 + g;
                vf0[ni] = Vb[d * AP + kk + l];
                vf1[ni] = Vb[d * AP + kk + l + 4];
            }
#pragma unroll
            for (int ni = 0; ni < 8; ni++)
                mma8(oa[ni], pa0, pa1, pa2, pa3, vf0[ni], vf1[ni]);
        }
    }

    // ---- epilogue: (H,B)->(B,T,H*dh) view permutation; g_ov as tf32 bits ----
    const int b2 = bh & 1, h2 = bh >> 1;
    const float inv0 = 1.f / l0r, inv1 = 1.f / l1r;
    const int t0 = qb + qr + g, t1 = t0 + 8;
#pragma unroll
    for (int ni = 0; ni < 8; ni++) {
        const int col = h2 * D_HEAD + ni * 8 + 2 * l;
        uint2 u;
        u.x = f2t(oa[ni][0] * inv0); u.y = f2t(oa[ni][1] * inv0);
        *(uint2*)&g_ov[(size_t)(b2 * T_ + t0) * D_MODEL + col] = u;
        u.x = f2t(oa[ni][2] * inv1); u.y = f2t(oa[ni][3] * inv1);
        *(uint2*)&g_ov[(size_t)(b2 * T_ + t1) * D_MODEL + col] = u;
    }
}

// ---------------- LayerNorm per row (residual already in g_y) ----------------
__global__ __launch_bounds__(256) void ln_kernel(const float* __restrict__ gamma,
                                                 const float* __restrict__ beta,
                                                 float* __restrict__ out) {
    __shared__ float red[8];
    const int row = blockIdx.x;
    const int tid = threadIdx.x;
    const float* yrow = g_y + (size_t)row * D_MODEL;

    float4 x = *(const float4*)(yrow + tid * 4);
    float s = x.x + x.y + x.z + x.w;
#pragma unroll
    for (int o = 16; o; o >>= 1) s += __shfl_xor_sync(0xffffffffu, s, o);
    if ((tid & 31) == 0) red[tid >> 5] = s;
    __syncthreads();
    s = red[0] + red[1] + red[2] + red[3] + red[4] + red[5] + red[6] + red[7];
    const float mu = s * (1.0f / D_MODEL);

    const float d0 = x.x - mu, d1 = x.y - mu, d2 = x.z - mu, d3 = x.w - mu;
    float v = d0 * d0 + d1 * d1 + d2 * d2 + d3 * d3;
#pragma unroll
    for (int o = 16; o; o >>= 1) v += __shfl_xor_sync(0xffffffffu, v, o);
    __syncthreads();
    if ((tid & 31) == 0) red[tid >> 5] = v;
    __syncthreads();
    v = red[0] + red[1] + red[2] + red[3] + red[4] + red[5] + red[6] + red[7];
    const float rstd = rsqrtf(v * (1.0f / D_MODEL) + 1e-5f);

    float4 gm = *(const float4*)(gamma + tid * 4);
    float4 bt = *(const float4*)(beta + tid * 4);
    float4 o4;
    o4.x = d0 * rstd * gm.x + bt.x;
    o4.y = d1 * rstd * gm.y + bt.y;
    o4.z = d2 * rstd * gm.z + bt.z;
    o4.w = d3 * rstd * gm.w + bt.w;
    *(float4*)(out + (size_t)row * D_MODEL + tid * 4) = o4;
}

// -----------------------------------------------------------------------------
extern "C" void kernel_launch(void* const* d_in, const int* in_sizes, int n_in,
                              void* d_out, int out_size) {
    const float* inp   = (const float*)d_in[0];
    const float* W_qkv = (const float*)d_in[1];
    const float* b_qkv = (const float*)d_in[2];
    const float* W_o   = (const float*)d_in[3];
    const float* gamma = (const float*)d_in[4];
    const float* beta  = (const float*)d_in[5];
    float* out = (float*)d_out;

    cudaFuncSetAttribute(qkv_gemm, cudaFuncAttributeMaxDynamicSharedMemorySize, GEMM_SMEM);
    cudaFuncSetAttribute(o_gemm,   cudaFuncAttributeMaxDynamicSharedMemorySize, GEMM_SMEM);
    cudaFuncSetAttribute(attn_kernel, cudaFuncAttributeMaxDynamicSharedMemorySize, ATT_SMEM);

    unsigned* d_inp_t;  cudaGetSymbolAddress((void**)&d_inp_t,  g_inp_t);
    unsigned* d_wqkv_t; cudaGetSymbolAddress((void**)&d_wqkv_t, g_wqkv_t);
    unsigned* d_wo_t;   cudaGetSymbolAddress((void**)&d_wo_t,   g_wo_t);

    cvt_kernel<<<(M_TOK * D_MODEL / 4 + 255) / 256, 256>>>(
        (const float4*)inp, (uint4*)d_inp_t, M_TOK * D_MODEL / 4);
    cvt_kernel<<<(N_QKV * D_MODEL / 4 + 255) / 256, 256>>>(
        (const float4*)W_qkv, (uint4*)d_wqkv_t, N_QKV * D_MODEL / 4);
    cvt_kernel<<<(D_MODEL * D_MODEL / 4 + 255) / 256, 256>>>(
        (const float4*)W_o, (uint4*)d_wo_t, D_MODEL * D_MODEL / 4);

    qkv_gemm<<<dim3(N_QKV / 128, M_TOK / 128), 256, GEMM_SMEM>>>(b_qkv);
    attn_kernel<<<dim3(T_ / 128, B_ * N_HEAD), 256, ATT_SMEM>>>();
    o_gemm<<<dim3(D_MODEL / 128, M_TOK / 128), 256, GEMM_SMEM>>>(inp);
    ln_kernel<<<M_TOK, 256>>>(gamma, beta, out);
}